// round 5
// baseline (speedup 1.0000x reference)
#include <cuda_runtime.h>
#include <cstdint>

// RoiAlign 3D, shapes fixed:
//   features: [B=4, C=128, H=64, W=64, T=64] fp32
//   rois:     [R=512, 7] (y0,x0,z0,y1,x1,z1,bidx), coords in [0,64]
//   out:      [R=512, C=128, 7,7,7] fp32
//
// R4: 181.7us; DRAM 38.5% (reads ~ tensor once = floor), L1TEX 71.8% = new
// bottleneck (~7 lines touched per warp-LDG x 8 scalar gathers/point).
// R5: stage the roi's rows in smem via aligned float4 LDGs (each line fetched
// ~once per block), interpolate from smem with scalar LDS. Cuts l1tex
// wavefronts ~1.5x; DRAM floor ~86us becomes the target.

#define RA_C     128
#define RA_DIM   64
#define RA_P     7
#define RA_PTS   343          // 7*7*7
#define RA_NROWS 196          // 14 y-slots * 14 x-slots (no dedup)
#define RA_ZP    68           // z pitch in floats (span<=64, 4-aligned, pad)
#define RA_SMEMB (RA_NROWS * RA_ZP * 4)   // 53312 bytes

__global__ __launch_bounds__(352) void roi_align_kernel(
    const float* __restrict__ feat,
    const float* __restrict__ rois,
    float* __restrict__ out)
{
    extern __shared__ float s_tile[];      // [196][68]

    __shared__ int   s_i0[21];   // clipped low index per (axis, p)
    __shared__ int   s_i1[21];   // clipped high index
    __shared__ float s_w[21];    // fractional weight
    __shared__ int   s_yval[14]; // y0[0..6], y1[0..6]
    __shared__ int   s_xval[14];
    __shared__ int   s_b, s_zbase, s_chunks;

    const int r   = blockIdx.x;   // roi (fast: all rois of a channel co-resident -> L2 reuse)
    const int c   = blockIdx.y;   // channel
    const int tid = threadIdx.x;

    // ---- per-axis sample setup ----
    if (tid < 21) {
        const int axis = tid / 7;          // 0=y 1=x 2=z
        const int p    = tid % 7;
        const float lo = __ldg(&rois[r * 7 + axis])     * (1.0f / 64.0f);
        const float hi = __ldg(&rois[r * 7 + 3 + axis]) * (1.0f / 64.0f);
        const float step = (float)p / 6.0f;
        const float cc = lo * 63.0f + step * (hi - lo) * 63.0f;
        const float c0 = floorf(cc);
        int i0 = (int)c0;
        int i1 = i0 + 1;
        i0 = min(max(i0, 0), RA_DIM - 1);
        i1 = min(max(i1, 0), RA_DIM - 1);
        s_i0[tid] = i0;
        s_i1[tid] = i1;
        s_w[tid]  = cc - c0;
    } else if (tid == 21) {
        s_b = (int)__ldg(&rois[r * 7 + 6]);
    }
    __syncthreads();

    if (tid < 7) {
        s_yval[tid]     = s_i0[tid];
        s_yval[7 + tid] = s_i1[tid];
    } else if (tid < 14) {
        const int p = tid - 7;
        s_xval[p]     = s_i0[7 + p];
        s_xval[7 + p] = s_i1[7 + p];
    } else if (tid == 14) {
        // z grid monotone (hi>=lo): min z0 at p=0, max z1 at p=6
        const int zb = s_i0[14] & ~3;               // 4-aligned
        s_zbase  = zb;
        s_chunks = (s_i1[20] - zb + 4) >> 2;        // ceil(span/4); never reads past z=63
    }
    __syncthreads();

    const int   b      = s_b;
    const int   zbase  = s_zbase;
    const int   chunks = s_chunks;
    const float* fb = feat + ((size_t)(b * RA_C + c) << 18);   // (y<<12)+(x<<6)+z

    // ---- stage rows: 196 rows x chunks float4 loads, coalesced & aligned ----
    const int nwork = RA_NROWS * chunks;
    for (int w = tid; w < nwork; w += 352) {
        const int row   = w / chunks;
        const int chunk = w - row * chunks;
        const int ys = row / 14;          // 0..13
        const int xs = row - ys * 14;
        const int y = s_yval[ys];
        const int x = s_xval[xs];
        const float4 v = *reinterpret_cast<const float4*>(
            fb + (y << 12) + (x << 6) + zbase + (chunk << 2));
        *reinterpret_cast<float4*>(&s_tile[row * RA_ZP + (chunk << 2)]) = v;
    }
    __syncthreads();

    // ---- interpolate from smem ----
    if (tid < RA_PTS) {
        const int py  = tid / 49;
        const int rem = tid - py * 49;
        const int px  = rem / 7;
        const int pz  = rem - px * 7;

        const float wy = s_w[py];
        const float wx = s_w[7 + px];
        const float wz = s_w[14 + pz];
        const int zo0 = s_i0[14 + pz] - zbase;
        const int zo1 = s_i1[14 + pz] - zbase;

        // row ids: y0 -> slot py, y1 -> slot 7+py; same for x
        const int r00 = (py * 14 + px) * RA_ZP;              // (y0,x0)
        const int r01 = (py * 14 + 7 + px) * RA_ZP;          // (y0,x1)
        const int r10 = ((7 + py) * 14 + px) * RA_ZP;        // (y1,x0)
        const int r11 = ((7 + py) * 14 + 7 + px) * RA_ZP;    // (y1,x1)

        const float f000 = s_tile[r00 + zo0];
        const float f001 = s_tile[r00 + zo1];
        const float f010 = s_tile[r01 + zo0];
        const float f011 = s_tile[r01 + zo1];
        const float f100 = s_tile[r10 + zo0];
        const float f101 = s_tile[r10 + zo1];
        const float f110 = s_tile[r11 + zo0];
        const float f111 = s_tile[r11 + zo1];

        const float iz = 1.0f - wz;
        const float ix = 1.0f - wx;
        const float iy = 1.0f - wy;

        const float v00 = iz * f000 + wz * f001;
        const float v01 = iz * f010 + wz * f011;
        const float v10 = iz * f100 + wz * f101;
        const float v11 = iz * f110 + wz * f111;

        const float v0 = ix * v00 + wx * v01;
        const float v1 = ix * v10 + wx * v11;

        out[((size_t)(r * RA_C + c)) * RA_PTS + tid] = iy * v0 + wy * v1;
    }
}

extern "C" void kernel_launch(void* const* d_in, const int* in_sizes, int n_in,
                              void* d_out, int out_size)
{
    const float* feat = (const float*)d_in[0];
    const float* rois = (const float*)d_in[1];
    float* out = (float*)d_out;

    // >48KB dynamic smem needs the opt-in attribute (idempotent, capture-safe)
    cudaFuncSetAttribute(roi_align_kernel,
                         cudaFuncAttributeMaxDynamicSharedMemorySize, RA_SMEMB);

    dim3 grid(512, RA_C);   // roi fast, channel slow
    roi_align_kernel<<<grid, 352, RA_SMEMB>>>(feat, rois, out);
}

// round 7
// speedup vs baseline: 3.1979x; 3.1979x over previous
#include <cuda_runtime.h>
#include <cstdint>

// RoiAlign 3D, shapes fixed:
//   features: [B=4, C=128, H=64, W=64, T=64] fp32
//   rois:     [R=512, 7] (y0,x0,z0,y1,x1,z1,bidx), coords in [0,64]
//   out:      [R=512, C=128, 7,7,7] fp32
//
// History: R4 (roi-fast grid, scalar 8-gather) = 181.7us, DRAM 38.5%
// (traffic at floor), L1 71.8%, issue 47.5% -> partly latency-bound.
// R5 smem staging REGRESSED (441us: STS+LDS doubled port traffic).
// R6: back to R4 scheme, 2 channels per block: gather addresses are
// channel-invariant -> compute once, 16 LDGs in flight per thread,
// setup amortized, writes stay contiguous (686 floats/block).

#define RA_C   128
#define RA_DIM 64
#define RA_P   7
#define RA_PTS (RA_P * RA_P * RA_P)   // 343

__global__ __launch_bounds__(352) void roi_align_kernel(
    const float* __restrict__ feat,
    const float* __restrict__ rois,
    float* __restrict__ out)
{
    const int r  = blockIdx.x;        // roi (fast dim -> cross-roi L2 reuse)
    const int c0 = blockIdx.y * 2;    // channel pair

    __shared__ int   s_i0[21];
    __shared__ int   s_i1[21];
    __shared__ float s_w[21];
    __shared__ int   s_b;

    const int tid = threadIdx.x;
    if (tid == 0) {
        s_b = (int)__ldg(&rois[r * 7 + 6]);
    }
    if (tid < 21) {
        const int axis = tid / 7;     // 0=y, 1=x, 2=z
        const int p    = tid % 7;
        const float lo = __ldg(&rois[r * 7 + axis])     * (1.0f / 64.0f);
        const float hi = __ldg(&rois[r * 7 + 3 + axis]) * (1.0f / 64.0f);
        const float step = (float)p / 6.0f;
        const float cc = lo * 63.0f + step * (hi - lo) * 63.0f;
        const float c0f = floorf(cc);
        int i0 = (int)c0f;
        int i1 = i0 + 1;
        i0 = min(max(i0, 0), RA_DIM - 1);
        i1 = min(max(i1, 0), RA_DIM - 1);
        s_i0[tid] = i0;
        s_i1[tid] = i1;
        s_w[tid]  = cc - c0f;
    }
    __syncthreads();

    if (tid >= RA_PTS) return;

    const int py  = tid / 49;
    const int rem = tid - py * 49;
    const int px  = rem / 7;
    const int pz  = rem - px * 7;

    const int   y0 = s_i0[py],      y1 = s_i1[py];
    const float wy = s_w[py];
    const int   x0 = s_i0[7 + px],  x1 = s_i1[7 + px];
    const float wx = s_w[7 + px];
    const int   z0 = s_i0[14 + pz], z1 = s_i1[14 + pz];
    const float wz = s_w[14 + pz];

    // base for (batch, channel): stride 64^3 = 1<<18 floats
    const float* fa = feat + ((size_t)(s_b * RA_C + c0) << 18);
    const float* fbp = fa + ((size_t)1 << 18);   // channel c0+1

    // addr(y,x,z) = (y<<12) + (x<<6) + z
    const int o000 = (y0 << 12) + (x0 << 6) + z0;
    const int o001 = (y0 << 12) + (x0 << 6) + z1;
    const int o010 = (y0 << 12) + (x1 << 6) + z0;
    const int o011 = (y0 << 12) + (x1 << 6) + z1;
    const int o100 = (y1 << 12) + (x0 << 6) + z0;
    const int o101 = (y1 << 12) + (x0 << 6) + z1;
    const int o110 = (y1 << 12) + (x1 << 6) + z0;
    const int o111 = (y1 << 12) + (x1 << 6) + z1;

    // 16 independent loads in flight
    const float a000 = __ldg(fa + o000);
    const float a001 = __ldg(fa + o001);
    const float a010 = __ldg(fa + o010);
    const float a011 = __ldg(fa + o011);
    const float a100 = __ldg(fa + o100);
    const float a101 = __ldg(fa + o101);
    const float a110 = __ldg(fa + o110);
    const float a111 = __ldg(fa + o111);
    const float b000 = __ldg(fbp + o000);
    const float b001 = __ldg(fbp + o001);
    const float b010 = __ldg(fbp + o010);
    const float b011 = __ldg(fbp + o011);
    const float b100 = __ldg(fbp + o100);
    const float b101 = __ldg(fbp + o101);
    const float b110 = __ldg(fbp + o110);
    const float b111 = __ldg(fbp + o111);

    const float iz = 1.0f - wz;
    const float ix = 1.0f - wx;
    const float iy = 1.0f - wy;

    const float a00 = iz * a000 + wz * a001;
    const float a01 = iz * a010 + wz * a011;
    const float a10 = iz * a100 + wz * a101;
    const float a11 = iz * a110 + wz * a111;
    const float b00 = iz * b000 + wz * b001;
    const float b01 = iz * b010 + wz * b011;
    const float b10 = iz * b100 + wz * b101;
    const float b11 = iz * b110 + wz * b111;

    const float a0 = ix * a00 + wx * a01;
    const float a1 = ix * a10 + wx * a11;
    const float b0 = ix * b00 + wx * b01;
    const float b1 = ix * b10 + wx * b11;

    float* ob = out + ((size_t)(r * RA_C + c0)) * RA_PTS;
    ob[tid]          = iy * a0 + wy * a1;
    ob[RA_PTS + tid] = iy * b0 + wy * b1;
}

extern "C" void kernel_launch(void* const* d_in, const int* in_sizes, int n_in,
                              void* d_out, int out_size)
{
    const float* feat = (const float*)d_in[0];
    const float* rois = (const float*)d_in[1];
    float* out = (float*)d_out;

    dim3 grid(512, RA_C / 2);   // roi fast, channel-pair slow
    roi_align_kernel<<<grid, 352>>>(feat, rois, out);
}